// round 12
// baseline (speedup 1.0000x reference)
#include <cuda_runtime.h>
#include <cuda_fp16.h>
#include <math.h>
#include <stdint.h>

#define B_ 32
#define T_ 2048
#define D_ 512
#define U_ 512

// ---------------------------------------------------------------------------
// score tiling: CTA = 32 rows x full U, 8 warps 1(M) x 8(N), warp tile 32x16.
// N-tiles of 128 u (4), k-chunks of 64 (8 per tile), double-buffered, occ 3.
// ---------------------------------------------------------------------------
#define MT 32
#define NTILE 128
#define KCH 64
#define A_STRIDE_B 1040       // 520 fp16 per row; %128==16 -> conflict-free ldsm
#define B_STRIDE_B 144        // 64 fp16 = 128B + 16 pad

// smem byte offsets
#define SM_A      0                       // 32*1040 = 33280
#define SM_B      33280                   // 2 bufs x 18432 = 36864
#define SM_B_BUF  18432
#define SM_PQ     70144                   // 512 f32
#define SM_V      72192                   // 512 f32
#define SM_RED    74240                   // 32*8 f32 = 1024
#define SMEM_TOTAL 75264                  // <= 228KB/3 -> occ 3

// ---------------------------------------------------------------------------
// scratch globals
// ---------------------------------------------------------------------------
__device__ float g_projq[B_ * U_];
__device__ float g_score[B_ * T_];
__device__ __align__(16) __half g_W1t[U_ * D_];   // [n][k] fp16

// ---------------------------------------------------------------------------
// PTX helpers (sm_80+ only; harness targets compute_103 -> no 'a' features)
// ---------------------------------------------------------------------------
__device__ __forceinline__ uint32_t smem_u32(const void* p) {
    uint32_t a;
    asm("{ .reg .u64 t; cvta.to.shared.u64 t, %1; cvt.u32.u64 %0, t; }"
        : "=r"(a) : "l"(p));
    return a;
}
__device__ __forceinline__ void cp_async16(uint32_t dst, const void* src) {
    asm volatile("cp.async.cg.shared.global [%0], [%1], 16;"
                 :: "r"(dst), "l"(src) : "memory");
}
#define CP_COMMIT() asm volatile("cp.async.commit_group;" ::: "memory")
#define CP_WAIT(n)  asm volatile("cp.async.wait_group %0;" :: "n"(n) : "memory")

__device__ __forceinline__ void ldsm4(uint32_t* r, uint32_t addr) {
    asm volatile("ldmatrix.sync.aligned.m8n8.x4.shared.b16 {%0,%1,%2,%3}, [%4];"
                 : "=r"(r[0]), "=r"(r[1]), "=r"(r[2]), "=r"(r[3]) : "r"(addr));
}
__device__ __forceinline__ void ldsm2(uint32_t* r, uint32_t addr) {
    asm volatile("ldmatrix.sync.aligned.m8n8.x2.shared.b16 {%0,%1}, [%2];"
                 : "=r"(r[0]), "=r"(r[1]) : "r"(addr));
}
__device__ __forceinline__ void mma_f16(float* d, const uint32_t* a, const uint32_t* b) {
    asm volatile(
        "mma.sync.aligned.m16n8k16.row.col.f32.f16.f16.f32 "
        "{%0,%1,%2,%3}, {%4,%5,%6,%7}, {%8,%9}, {%0,%1,%2,%3};"
        : "+f"(d[0]), "+f"(d[1]), "+f"(d[2]), "+f"(d[3])
        : "r"(a[0]), "r"(a[1]), "r"(a[2]), "r"(a[3]), "r"(b[0]), "r"(b[1]));
}

__device__ __forceinline__ float tanh_fast(float x) {
    float xc = fminf(fmaxf(x, -9.0f), 9.0f);
    float e = __expf(2.0f * xc);
    return (e - 1.0f) / (e + 1.0f);
}

// ---------------------------------------------------------------------------
// fused prep: blocks [0,512) transpose+convert W1; blocks [512,544) projq
// ---------------------------------------------------------------------------
__global__ void prep_kernel(const float* __restrict__ W1,
                            const float* __restrict__ query,
                            const float* __restrict__ W2,
                            const float* __restrict__ b1,
                            const float* __restrict__ b2) {
    if (blockIdx.x < 512) {
        int k = blockIdx.x;
        int n = threadIdx.x;
        g_W1t[n * D_ + k] = __float2half_rn(W1[k * U_ + n]);
    } else {
        __shared__ float q[D_];
        int b = blockIdx.x - 512;
        q[threadIdx.x] = query[b * D_ + threadIdx.x];
        __syncthreads();
        int u = threadIdx.x;
        float acc = b1[u] + b2[u];
#pragma unroll 8
        for (int d = 0; d < D_; d++) acc += q[d] * W2[d * U_ + u];
        g_projq[b * U_ + u] = acc;
    }
}

// ---------------------------------------------------------------------------
// score kernel: fp16 mma.sync GEMM, MT=32, occ 3, fused tanh/V epilogue
// ---------------------------------------------------------------------------
__global__ void __launch_bounds__(256, 3)
score_kernel(const float* __restrict__ values, const float* __restrict__ V) {
    extern __shared__ char smem[];
    const uint32_t sb = smem_u32(smem);
    const int tid = threadIdx.x;
    const int wn = tid >> 5;           // 0..7: 16-u group within 128-u N-tile
    const int lane = tid & 31;
    const int row0 = blockIdx.x * MT;
    const int b = row0 / T_;

    // ---- preload B chunk 0 (nt=0, kc=0): 128n x 64k fp16 = 1024 x 16B ----
    {
#pragma unroll
        for (int it = 0; it < 4; it++) {
            int idx = tid + it * 256;
            int n = idx >> 3, c = idx & 7;
            uint32_t dst = sb + SM_B + n * B_STRIDE_B + c * 16;
            cp_async16(dst, g_W1t + (size_t)n * D_ + c * 8);
        }
        CP_COMMIT();
    }

    // ---- stage pq + V ----
    {
        float* pqs = (float*)(smem + SM_PQ);
        float* Vs = (float*)(smem + SM_V);
        for (int i = tid; i < U_; i += 256) {
            pqs[i] = g_projq[b * U_ + i];
            Vs[i] = V[i];
        }
    }

    // ---- convert A (values[32 x 512]) fp32 -> fp16 in smem ----
    {
        const float4* src = (const float4*)(values + (size_t)row0 * D_);
#pragma unroll
        for (int it = 0; it < 16; it++) {
            int idx = tid + it * 256;           // 4096 float4
            int r = idx >> 7, c = idx & 127;
            float4 v = src[idx];
            __half2 p0 = __floats2half2_rn(v.x, v.y);
            __half2 p1 = __floats2half2_rn(v.z, v.w);
            uint32_t off = r * A_STRIDE_B + c * 8;
            *(__half2*)(smem + SM_A + off) = p0;
            *(__half2*)(smem + SM_A + off + 4) = p1;
        }
    }

    // ---- ldmatrix lane bases ----
    const uint32_t a_lane = (uint32_t)(((lane & 7) + ((lane >> 3) & 1) * 8) * A_STRIDE_B
                                       + (lane >> 4) * 16);
    const uint32_t a_base = sb + SM_A + a_lane;                 // rows 0..31
    const uint32_t b_lane = (uint32_t)((lane & 7) * B_STRIDE_B + ((lane >> 3) & 1) * 16);
    const uint32_t b_base = sb + SM_B + (uint32_t)(wn * 16) * B_STRIDE_B + b_lane;

    float acc[2][2][4];                 // [mf: rows 0-15/16-31][nf: n+0/8]
#pragma unroll
    for (int mf = 0; mf < 2; mf++)
#pragma unroll
        for (int nf = 0; nf < 2; nf++)
#pragma unroll
            for (int j = 0; j < 4; j++) acc[mf][nf][j] = 0.f;
    float sp[4] = {0.f, 0.f, 0.f, 0.f};

    const float* pqs = (const float*)(smem + SM_PQ);
    const float* Vs = (const float*)(smem + SM_V);

    for (int i = 0; i < 32; i++) {              // nt = i>>3, kc = i&7
        const int nt = i >> 3;
        const int kc = i & 7;
        const int buf = i & 1;

        if (i + 1 < 32) {                       // prefetch next B chunk
            const int nn = (i + 1) >> 3, nk = (i + 1) & 7, nb = (i + 1) & 1;
#pragma unroll
            for (int it = 0; it < 4; it++) {
                int idx = tid + it * 256;
                int n = idx >> 3, c = idx & 7;
                uint32_t dst = sb + SM_B + nb * SM_B_BUF + n * B_STRIDE_B + c * 16;
                cp_async16(dst, g_W1t + (size_t)(nn * NTILE + n) * D_ + nk * KCH + c * 8);
            }
            CP_COMMIT();
            CP_WAIT(1);
        } else {
            CP_WAIT(0);
        }
        __syncthreads();

        // ---- compute chunk: 4 ksteps of k16 ----
        const uint32_t ab = a_base + (uint32_t)kc * 128;        // 64 fp16 = 128B
        const uint32_t bb = b_base + (uint32_t)buf * SM_B_BUF;
#pragma unroll
        for (int ks = 0; ks < 4; ks++) {
            uint32_t ah[2][4], bh[2][2];
            ldsm4(ah[0], ab + ks * 32);                          // rows 0-15
            ldsm4(ah[1], ab + 16 * A_STRIDE_B + ks * 32);        // rows 16-31
            ldsm2(bh[0], bb + ks * 32);                          // n +0..7
            ldsm2(bh[1], bb + 8 * B_STRIDE_B + ks * 32);         // n +8..15
#pragma unroll
            for (int mf = 0; mf < 2; mf++)
#pragma unroll
                for (int nf = 0; nf < 2; nf++)
                    mma_f16(acc[mf][nf], ah[mf], bh[nf]);
        }

        if (kc == 7) {
            // ---- epilogue for N-tile nt ----
#pragma unroll
            for (int mf = 0; mf < 2; mf++)
#pragma unroll
                for (int nf = 0; nf < 2; nf++) {
                    int u0 = nt * NTILE + wn * 16 + nf * 8 + (lane & 3) * 2;
                    float pq0 = pqs[u0], pq1 = pqs[u0 + 1];
                    float v0 = Vs[u0], v1 = Vs[u0 + 1];
                    sp[mf * 2 + 0] += tanh_fast(acc[mf][nf][0] + pq0) * v0
                                    + tanh_fast(acc[mf][nf][1] + pq1) * v1;
                    sp[mf * 2 + 1] += tanh_fast(acc[mf][nf][2] + pq0) * v0
                                    + tanh_fast(acc[mf][nf][3] + pq1) * v1;
#pragma unroll
                    for (int j = 0; j < 4; j++) acc[mf][nf][j] = 0.f;
                }
        }
        __syncthreads();
    }

    // ---- reduce score partials ----
    // sp[mf*2+0] -> row mf*16 + (lane>>2); sp[mf*2+1] -> row mf*16 + 8 + (lane>>2)
#pragma unroll
    for (int j = 0; j < 4; j++) {
        sp[j] += __shfl_xor_sync(0xffffffffu, sp[j], 1);
        sp[j] += __shfl_xor_sync(0xffffffffu, sp[j], 2);
    }
    float* red = (float*)(smem + SM_RED);
    if ((lane & 3) == 0) {
        int g = lane >> 2;
#pragma unroll
        for (int mf = 0; mf < 2; mf++) {
            int r0 = mf * 16 + g;
            red[r0 * 8 + wn] = sp[mf * 2 + 0];
            red[(r0 + 8) * 8 + wn] = sp[mf * 2 + 1];
        }
    }
    __syncthreads();
    if (tid < MT) {
        float s = 0.f;
#pragma unroll
        for (int j = 0; j < 8; j++) s += red[tid * 8 + j];
        g_score[row0 + tid] = s;
    }
}

// ---------------------------------------------------------------------------
// softmax over T per batch -> weights; zero context region
// ---------------------------------------------------------------------------
__global__ void softmax_kernel(float* __restrict__ out) {
    __shared__ float sdata[256];
    const int b = blockIdx.x, tid = threadIdx.x;
    float s[8];
    float mx = -1e30f;
#pragma unroll
    for (int i = 0; i < 8; i++) {
        s[i] = g_score[b * T_ + tid + i * 256];
        mx = fmaxf(mx, s[i]);
    }
    sdata[tid] = mx;
    __syncthreads();
    for (int off = 128; off > 0; off >>= 1) {
        if (tid < off) sdata[tid] = fmaxf(sdata[tid], sdata[tid + off]);
        __syncthreads();
    }
    mx = sdata[0];
    __syncthreads();
    float sum = 0.f;
#pragma unroll
    for (int i = 0; i < 8; i++) {
        s[i] = __expf(s[i] - mx);
        sum += s[i];
    }
    sdata[tid] = sum;
    __syncthreads();
    for (int off = 128; off > 0; off >>= 1) {
        if (tid < off) sdata[tid] += sdata[tid + off];
        __syncthreads();
    }
    float inv = 1.0f / sdata[0];
    float* w = out + B_ * D_;
#pragma unroll
    for (int i = 0; i < 8; i++) w[b * T_ + tid + i * 256] = s[i] * inv;

    out[b * D_ + tid] = 0.f;
    out[b * D_ + 256 + tid] = 0.f;
}

// ---------------------------------------------------------------------------
// context[b,d] = sum_t w[b,t] * values[b,t,d]  (R10 keeper config)
// grid (32, 32) x 128 threads: 64 t per block, unroll 8
// ---------------------------------------------------------------------------
__global__ void __launch_bounds__(128)
context_kernel(const float* __restrict__ values, float* __restrict__ out) {
    const int b = blockIdx.x;
    const int t0 = blockIdx.y * 64;
    const int tid = threadIdx.x;
    __shared__ float ws[64];
    if (tid < 64) ws[tid] = out[B_ * D_ + b * T_ + t0 + tid];
    __syncthreads();
    const float4* vp = (const float4*)(values + ((size_t)b * T_ + t0) * D_) + tid;
    float ax = 0.f, ay = 0.f, az = 0.f, aw = 0.f;
#pragma unroll 8
    for (int tt = 0; tt < 64; tt++) {
        float w = ws[tt];
        float4 v = vp[tt * 128];
        ax += w * v.x; ay += w * v.y; az += w * v.z; aw += w * v.w;
    }
    float* o = out + b * D_ + tid * 4;
    atomicAdd(o + 0, ax);
    atomicAdd(o + 1, ay);
    atomicAdd(o + 2, az);
    atomicAdd(o + 3, aw);
}

// ---------------------------------------------------------------------------
extern "C" void kernel_launch(void* const* d_in, const int* in_sizes, int n_in,
                              void* d_out, int out_size) {
    const float* values = (const float*)d_in[0];
    const float* query  = (const float*)d_in[1];
    const float* W1     = (const float*)d_in[2];
    const float* b1     = (const float*)d_in[3];
    const float* W2     = (const float*)d_in[4];
    const float* b2     = (const float*)d_in[5];
    const float* V      = (const float*)d_in[6];
    // d_in[7] = bV: softmax shift-invariant -> unused
    float* out = (float*)d_out;

    cudaFuncSetAttribute(score_kernel,
                         cudaFuncAttributeMaxDynamicSharedMemorySize, SMEM_TOTAL);

    prep_kernel<<<544, 512>>>(W1, query, W2, b1, b2);
    score_kernel<<<(B_ * T_) / MT, 256, SMEM_TOTAL>>>(values, V);
    softmax_kernel<<<B_, 256>>>(out);
    context_kernel<<<dim3(B_, 32), 128>>>(values, out);
}

// round 14
// speedup vs baseline: 1.1491x; 1.1491x over previous
#include <cuda_runtime.h>
#include <cuda_fp16.h>
#include <math.h>
#include <stdint.h>

#define B_ 32
#define T_ 2048
#define D_ 512
#define U_ 512

// ---------------------------------------------------------------------------
// score tiling (R8 shape): CTA = 64 rows x full U, 8 warps 2(M) x 4(N),
// warp tile 32x16, N-tiles of 64 u, B chunks k=128 double-buffered, fp16 MMA.
// B staging + sync scoped to the 2-warp pair sharing each wn slab.
// ---------------------------------------------------------------------------
#define MT 64
#define NTILE 64
#define KCH 128
#define A_STRIDE_B 1040       // 520 fp16 per row; %128==16 -> conflict-free ldsm
#define B_STRIDE_B 272        // 136 fp16 per row

// smem byte offsets
#define SM_A      0                       // 64*1040 = 66560
#define SM_B      66560                   // 2 bufs x 17408
#define SM_B_BUF  17408
#define SM_PQ     101376
#define SM_V      103424
#define SM_RED    105472
#define SMEM_TOTAL 106496

// ---------------------------------------------------------------------------
// scratch globals
// ---------------------------------------------------------------------------
__device__ float g_projq[B_ * U_];
__device__ float g_score[B_ * T_];
__device__ __align__(16) __half g_W1t[U_ * D_];   // [n][k] fp16

// ---------------------------------------------------------------------------
// PTX helpers (sm_80+ only; harness targets compute_103 -> no 'a' features)
// ---------------------------------------------------------------------------
__device__ __forceinline__ uint32_t smem_u32(const void* p) {
    uint32_t a;
    asm("{ .reg .u64 t; cvta.to.shared.u64 t, %1; cvt.u32.u64 %0, t; }"
        : "=r"(a) : "l"(p));
    return a;
}
__device__ __forceinline__ void cp_async16(uint32_t dst, const void* src) {
    asm volatile("cp.async.cg.shared.global [%0], [%1], 16;"
                 :: "r"(dst), "l"(src) : "memory");
}
#define CP_COMMIT() asm volatile("cp.async.commit_group;" ::: "memory")
#define CP_WAIT(n)  asm volatile("cp.async.wait_group %0;" :: "n"(n) : "memory")
#define PAIR_BAR(id) asm volatile("bar.sync %0, 64;" :: "r"(id) : "memory")

__device__ __forceinline__ void ldsm4(uint32_t* r, uint32_t addr) {
    asm volatile("ldmatrix.sync.aligned.m8n8.x4.shared.b16 {%0,%1,%2,%3}, [%4];"
                 : "=r"(r[0]), "=r"(r[1]), "=r"(r[2]), "=r"(r[3]) : "r"(addr));
}
__device__ __forceinline__ void ldsm2(uint32_t* r, uint32_t addr) {
    asm volatile("ldmatrix.sync.aligned.m8n8.x2.shared.b16 {%0,%1}, [%2];"
                 : "=r"(r[0]), "=r"(r[1]) : "r"(addr));
}
__device__ __forceinline__ void mma_f16(float* d, const uint32_t* a, const uint32_t* b) {
    asm volatile(
        "mma.sync.aligned.m16n8k16.row.col.f32.f16.f16.f32 "
        "{%0,%1,%2,%3}, {%4,%5,%6,%7}, {%8,%9}, {%0,%1,%2,%3};"
        : "+f"(d[0]), "+f"(d[1]), "+f"(d[2]), "+f"(d[3])
        : "r"(a[0]), "r"(a[1]), "r"(a[2]), "r"(a[3]), "r"(b[0]), "r"(b[1]));
}

__device__ __forceinline__ float tanh_fast(float x) {
    float xc = fminf(fmaxf(x, -9.0f), 9.0f);
    float e = __expf(2.0f * xc);
    return (e - 1.0f) / (e + 1.0f);
}

// ---------------------------------------------------------------------------
// fused prep: blocks [0,512) transpose+convert W1; blocks [512,544) projq
// ---------------------------------------------------------------------------
__global__ void prep_kernel(const float* __restrict__ W1,
                            const float* __restrict__ query,
                            const float* __restrict__ W2,
                            const float* __restrict__ b1,
                            const float* __restrict__ b2) {
    if (blockIdx.x < 512) {
        int k = blockIdx.x;
        int n = threadIdx.x;
        g_W1t[n * D_ + k] = __float2half_rn(W1[k * U_ + n]);
    } else {
        __shared__ float q[D_];
        int b = blockIdx.x - 512;
        q[threadIdx.x] = query[b * D_ + threadIdx.x];
        __syncthreads();
        int u = threadIdx.x;
        float acc = b1[u] + b2[u];
#pragma unroll 8
        for (int d = 0; d < D_; d++) acc += q[d] * W2[d * U_ + u];
        g_projq[b * U_ + u] = acc;
    }
}

// ---------------------------------------------------------------------------
// score kernel: fp16 mma.sync GEMM, pair-scoped B staging + named barriers
// ---------------------------------------------------------------------------
__global__ void __launch_bounds__(256, 2)
score_kernel(const float* __restrict__ values, const float* __restrict__ V) {
    extern __shared__ char smem[];
    const uint32_t sb = smem_u32(smem);
    const int tid = threadIdx.x;
    const int wid = tid >> 5;
    const int lane = tid & 31;
    const int wm = wid & 1;
    const int wn = wid >> 1;
    const int ptid = (wm << 5) | lane;          // 0..63 within the wn-pair
    const int bar_id = wn + 1;                  // named barrier per pair
    const int row0 = blockIdx.x * MT;
    const int b = row0 / T_;

    // pair wn owns B rows [wn*16, wn*16+16). Per chunk: 256 x 16B, 4 per thread.
    const uint32_t bdst0 = sb + SM_B + (uint32_t)(wn * 16) * B_STRIDE_B;

    // ---- preload B chunk 0 (pair-split) ----
    {
#pragma unroll
        for (int it = 0; it < 4; it++) {
            int idx = ptid + it * 64;           // 256 chunks for this pair
            int nl = idx >> 4, c = idx & 15;
            cp_async16(bdst0 + nl * B_STRIDE_B + c * 16,
                       g_W1t + (size_t)(wn * 16 + nl) * D_ + c * 8);
        }
        CP_COMMIT();
    }

    // ---- stage pq + V ----
    {
        float* pqs = (float*)(smem + SM_PQ);
        float* Vs = (float*)(smem + SM_V);
        for (int i = tid; i < U_; i += 256) {
            pqs[i] = g_projq[b * U_ + i];
            Vs[i] = V[i];
        }
    }

    // ---- convert A (values[64 x 512]) fp32 -> fp16 in smem ----
    {
        const float4* src = (const float4*)(values + (size_t)row0 * D_);
#pragma unroll
        for (int it = 0; it < 32; it++) {
            int idx = tid + it * 256;
            int r = idx >> 7, c = idx & 127;
            float4 v = src[idx];
            __half2 p0 = __floats2half2_rn(v.x, v.y);
            __half2 p1 = __floats2half2_rn(v.z, v.w);
            uint32_t off = r * A_STRIDE_B + c * 8;
            *(__half2*)(smem + SM_A + off) = p0;
            *(__half2*)(smem + SM_A + off + 4) = p1;
        }
    }
    __syncthreads();   // A + pq/V visible block-wide

    // ---- ldmatrix lane bases ----
    const uint32_t a_lane = (uint32_t)(((lane & 7) + ((lane >> 3) & 1) * 8) * A_STRIDE_B
                                       + (lane >> 4) * 16);
    const uint32_t a_base = sb + SM_A + (uint32_t)(wm * 32) * A_STRIDE_B + a_lane;
    const uint32_t b_lane = (uint32_t)((lane & 7) * B_STRIDE_B + ((lane >> 3) & 1) * 16);
    const uint32_t b_base = sb + SM_B + (uint32_t)(wn * 16) * B_STRIDE_B + b_lane;

    float acc[2][2][4];
#pragma unroll
    for (int mf = 0; mf < 2; mf++)
#pragma unroll
        for (int nf = 0; nf < 2; nf++)
#pragma unroll
            for (int j = 0; j < 4; j++) acc[mf][nf][j] = 0.f;
    float sp[4] = {0.f, 0.f, 0.f, 0.f};

    const float* pqs = (const float*)(smem + SM_PQ);
    const float* Vs = (const float*)(smem + SM_V);

    for (int i = 0; i < 32; i++) {              // nt = i>>2, kc = i&3
        const int nt = i >> 2;
        const int kc = i & 3;
        const int buf = i & 1;

        if (i + 1 < 32) {                       // pair-split prefetch next chunk
            const int nn = (i + 1) >> 2, nk = (i + 1) & 3, nb = (i + 1) & 1;
            const uint32_t dstb = bdst0 + (uint32_t)nb * SM_B_BUF;
#pragma unroll
            for (int it = 0; it < 4; it++) {
                int idx = ptid + it * 64;
                int nl = idx >> 4, c = idx & 15;
                cp_async16(dstb + nl * B_STRIDE_B + c * 16,
                           g_W1t + (size_t)(nn * NTILE + wn * 16 + nl) * D_
                                 + nk * KCH + c * 8);
            }
            CP_COMMIT();
            CP_WAIT(1);
        } else {
            CP_WAIT(0);
        }
        PAIR_BAR(bar_id);                       // partner's chunk-i copies done

        const uint32_t ab = a_base + (uint32_t)kc * 256;
        const uint32_t bb = b_base + (uint32_t)buf * SM_B_BUF;
#pragma unroll
        for (int ks = 0; ks < 8; ks++) {
            uint32_t ah[2][4], bh[2][2];
            ldsm4(ah[0], ab + ks * 32);
            ldsm4(ah[1], ab + 16 * A_STRIDE_B + ks * 32);
            ldsm2(bh[0], bb + ks * 32);
            ldsm2(bh[1], bb + 8 * B_STRIDE_B + ks * 32);
#pragma unroll
            for (int mf = 0; mf < 2; mf++)
#pragma unroll
                for (int nf = 0; nf < 2; nf++)
                    mma_f16(acc[mf][nf], ah[mf], bh[nf]);
        }

        if (kc == 3) {
            // ---- epilogue for N-tile nt (register-local) ----
#pragma unroll
            for (int mf = 0; mf < 2; mf++)
#pragma unroll
                for (int nf = 0; nf < 2; nf++) {
                    int u0 = nt * NTILE + wn * 16 + nf * 8 + (lane & 3) * 2;
                    float pq0 = pqs[u0], pq1 = pqs[u0 + 1];
                    float v0 = Vs[u0], v1 = Vs[u0 + 1];
                    sp[mf * 2 + 0] += tanh_fast(acc[mf][nf][0] + pq0) * v0
                                    + tanh_fast(acc[mf][nf][1] + pq1) * v1;
                    sp[mf * 2 + 1] += tanh_fast(acc[mf][nf][2] + pq0) * v0
                                    + tanh_fast(acc[mf][nf][3] + pq1) * v1;
#pragma unroll
                    for (int j = 0; j < 4; j++) acc[mf][nf][j] = 0.f;
                }
        }
        PAIR_BAR(bar_id);                       // pair done reading chunk i
    }

    // ---- reduce score partials ----
#pragma unroll
    for (int j = 0; j < 4; j++) {
        sp[j] += __shfl_xor_sync(0xffffffffu, sp[j], 1);
        sp[j] += __shfl_xor_sync(0xffffffffu, sp[j], 2);
    }
    float* red = (float*)(smem + SM_RED);
    if ((lane & 3) == 0) {
        int g = lane >> 2;
#pragma unroll
        for (int mf = 0; mf < 2; mf++) {
            int r0 = wm * 32 + mf * 16 + g;
            red[r0 * 4 + wn] = sp[mf * 2 + 0];
            red[(r0 + 8) * 4 + wn] = sp[mf * 2 + 1];
        }
    }
    __syncthreads();
    if (tid < MT) {
        g_score[row0 + tid] = red[tid * 4] + red[tid * 4 + 1]
                            + red[tid * 4 + 2] + red[tid * 4 + 3];
    }
}

// ---------------------------------------------------------------------------
// softmax over T per batch -> weights; zero context region
// ---------------------------------------------------------------------------
__global__ void softmax_kernel(float* __restrict__ out) {
    __shared__ float sdata[256];
    const int b = blockIdx.x, tid = threadIdx.x;
    float s[8];
    float mx = -1e30f;
#pragma unroll
    for (int i = 0; i < 8; i++) {
        s[i] = g_score[b * T_ + tid + i * 256];
        mx = fmaxf(mx, s[i]);
    }
    sdata[tid] = mx;
    __syncthreads();
    for (int off = 128; off > 0; off >>= 1) {
        if (tid < off) sdata[tid] = fmaxf(sdata[tid], sdata[tid + off]);
        __syncthreads();
    }
    mx = sdata[0];
    __syncthreads();
    float sum = 0.f;
#pragma unroll
    for (int i = 0; i < 8; i++) {
        s[i] = __expf(s[i] - mx);
        sum += s[i];
    }
    sdata[tid] = sum;
    __syncthreads();
    for (int off = 128; off > 0; off >>= 1) {
        if (tid < off) sdata[tid] += sdata[tid + off];
        __syncthreads();
    }
    float inv = 1.0f / sdata[0];
    float* w = out + B_ * D_;
#pragma unroll
    for (int i = 0; i < 8; i++) w[b * T_ + tid + i * 256] = s[i] * inv;

    out[b * D_ + tid] = 0.f;
    out[b * D_ + 256 + tid] = 0.f;
}

// ---------------------------------------------------------------------------
// context[b,d] = sum_t w[b,t] * values[b,t,d]  (R10 keeper config)
// grid (32, 32) x 128 threads: 64 t per block, unroll 8
// ---------------------------------------------------------------------------
__global__ void __launch_bounds__(128)
context_kernel(const float* __restrict__ values, float* __restrict__ out) {
    const int b = blockIdx.x;
    const int t0 = blockIdx.y * 64;
    const int tid = threadIdx.x;
    __shared__ float ws[64];
    if (tid < 64) ws[tid] = out[B_ * D_ + b * T_ + t0 + tid];
    __syncthreads();
    const float4* vp = (const float4*)(values + ((size_t)b * T_ + t0) * D_) + tid;
    float ax = 0.f, ay = 0.f, az = 0.f, aw = 0.f;
#pragma unroll 8
    for (int tt = 0; tt < 64; tt++) {
        float w = ws[tt];
        float4 v = vp[tt * 128];
        ax += w * v.x; ay += w * v.y; az += w * v.z; aw += w * v.w;
    }
    float* o = out + b * D_ + tid * 4;
    atomicAdd(o + 0, ax);
    atomicAdd(o + 1, ay);
    atomicAdd(o + 2, az);
    atomicAdd(o + 3, aw);
}

// ---------------------------------------------------------------------------
extern "C" void kernel_launch(void* const* d_in, const int* in_sizes, int n_in,
                              void* d_out, int out_size) {
    const float* values = (const float*)d_in[0];
    const float* query  = (const float*)d_in[1];
    const float* W1     = (const float*)d_in[2];
    const float* b1     = (const float*)d_in[3];
    const float* W2     = (const float*)d_in[4];
    const float* b2     = (const float*)d_in[5];
    const float* V      = (const float*)d_in[6];
    // d_in[7] = bV: softmax shift-invariant -> unused
    float* out = (float*)d_out;

    cudaFuncSetAttribute(score_kernel,
                         cudaFuncAttributeMaxDynamicSharedMemorySize, SMEM_TOTAL);

    prep_kernel<<<544, 512>>>(W1, query, W2, b1, b2);
    score_kernel<<<(B_ * T_) / MT, 256, SMEM_TOTAL>>>(values, V);
    softmax_kernel<<<B_, 256>>>(out);
    context_kernel<<<dim3(B_, 32), 128>>>(values, out);
}